// round 7
// baseline (speedup 1.0000x reference)
#include <cuda_runtime.h>
#include <cuda_fp16.h>
#include <cstdint>

// MinimalRNNCell, two-phase, all weights register-resident:
//   Phase 1: g_xk = x @ K                  (parallel GEMM)
//   Phase 2: h_t = g_xk[t] + h_{t-1} @ R   (chunked scan, 32-step warm-up)
// mma.sync.m16n8k16, fp16 hi/lo x3 (Ahi*Bhi + Ahi*Blo + Alo*Bhi), err ~2^-22.
// K=128 per GEMM => full weight frags (hi+lo) = 128 regs/thread, zero A
// crossbar traffic and no spills (prior rounds pinned at 255 regs).

#define NB 256
#define NT 2048
#define ND 128
#define NU 128
#define BT (NB * NT)          // 524288
#define ROWS 32
#define CHUNK 128
#define WARM 32

#define PITCH 272             // bytes/row; (272/4)%32==4 -> conflict-free frags

// Phase 1
#define P1_ROWS 32
#define P1_TPB  16
#define P1_GRID (BT / P1_ROWS / P1_TPB)   // 1024
#define XBUF(b, hl) (((b) * 2 + (hl)) * (P1_ROWS * PITCH))
#define SMEM1 (4 * P1_ROWS * PITCH)       // 34816

// Phase 2
#define HB(b, hl) (((b) * 2 + (hl)) * (ROWS * PITCH))
#define SMEM2 (4 * ROWS * PITCH)          // 34816

__device__ float g_xk[(size_t)BT * NU];   // 268 MB scratch

__device__ __forceinline__ void mma16816(float* c, const uint32_t* a,
                                         uint32_t b0, uint32_t b1) {
    asm("mma.sync.aligned.m16n8k16.row.col.f32.f16.f16.f32 "
        "{%0,%1,%2,%3}, {%4,%5,%6,%7}, {%8,%9}, {%0,%1,%2,%3};"
        : "+f"(c[0]), "+f"(c[1]), "+f"(c[2]), "+f"(c[3])
        : "r"(a[0]), "r"(a[1]), "r"(a[2]), "r"(a[3]), "r"(b0), "r"(b1));
}

__device__ __forceinline__ uint32_t pack_hilo(float f0, float f1, uint32_t* lo) {
    __half h0 = __float2half_rn(f0), h1 = __float2half_rn(f1);
    __half l0 = __float2half_rn(f0 - __half2float(h0));
    __half l1 = __float2half_rn(f1 - __half2float(h1));
    *lo = (uint32_t)__half_as_ushort(l0) | ((uint32_t)__half_as_ushort(l1) << 16);
    return (uint32_t)__half_as_ushort(h0) | ((uint32_t)__half_as_ushort(h1) << 16);
}

// All weight frags (hi + lo) into registers for a 128x128 W[d][u].
__device__ __forceinline__ void build_w_regs(const float* __restrict__ W,
                                             uint32_t ahi[2][8][4],
                                             uint32_t alo[2][8][4],
                                             int u0, int gid, int tig) {
#pragma unroll
    for (int mt = 0; mt < 2; ++mt) {
        const int ur0 = u0 + mt * 16 + gid, ur1 = ur0 + 8;
#pragma unroll
        for (int ks = 0; ks < 8; ++ks) {
            const int d = ks * 16 + 2 * tig;
            ahi[mt][ks][0] = pack_hilo(W[d * NU + ur0], W[(d + 1) * NU + ur0], &alo[mt][ks][0]);
            ahi[mt][ks][1] = pack_hilo(W[d * NU + ur1], W[(d + 1) * NU + ur1], &alo[mt][ks][1]);
            ahi[mt][ks][2] = pack_hilo(W[(d + 8) * NU + ur0], W[(d + 9) * NU + ur0], &alo[mt][ks][2]);
            ahi[mt][ks][3] = pack_hilo(W[(d + 8) * NU + ur1], W[(d + 9) * NU + ur1], &alo[mt][ks][3]);
        }
    }
}

// =================== Phase 1: g_xk = x @ K ===================
__global__ __launch_bounds__(256, 1)
void xk_kernel(const float* __restrict__ x, const float* __restrict__ K) {
    extern __shared__ char sm[];
    const int tid  = threadIdx.x;
    const int lane = tid & 31;
    const int wid  = tid >> 5;
    const int gid  = lane >> 2, tig = lane & 3;
    const int mgrp = wid & 3, ngrp = wid >> 2;
    const int u0   = mgrp * 32;

    uint32_t ahi[2][8][4], alo[2][8][4];
    build_w_regs(K, ahi, alo, u0, gid, tig);

    const long long tile0 = (long long)blockIdx.x * P1_TPB;
    const float4* x4 = (const float4*)x;

    float4 px[4];
#pragma unroll
    for (int j = 0; j < 4; ++j) {
        const int idx = tid + j * 256;
        px[j] = x4[(tile0 * P1_ROWS + (idx >> 5)) * 32 + (idx & 31)];
    }

    int cur = 0;
    for (int it = 0; it < P1_TPB; ++it) {
        // ---- stage prefetched x tile (hi/lo) ----
#pragma unroll
        for (int j = 0; j < 4; ++j) {
            const int idx = tid + j * 256;
            const int r = idx >> 5, c4 = idx & 31;
            uint32_t lo0, lo1;
            const uint32_t h0 = pack_hilo(px[j].x, px[j].y, &lo0);
            const uint32_t h1 = pack_hilo(px[j].z, px[j].w, &lo1);
            char* bh = sm + XBUF(cur, 0) + r * PITCH + c4 * 8;
            char* bl = sm + XBUF(cur, 1) + r * PITCH + c4 * 8;
            *(uint32_t*)bh = h0;  *(uint32_t*)(bh + 4) = h1;
            *(uint32_t*)bl = lo0; *(uint32_t*)(bl + 4) = lo1;
        }
        __syncthreads();

        // ---- prefetch next tile (hidden under MMA) ----
        if (it + 1 < P1_TPB) {
#pragma unroll
            for (int j = 0; j < 4; ++j) {
                const int idx = tid + j * 256;
                px[j] = x4[((tile0 + it + 1) * P1_ROWS + (idx >> 5)) * 32 + (idx & 31)];
            }
        }

        // ---- MMA: 32 u x 16 rows per warp ----
        float c[2][2][4];
#pragma unroll
        for (int i = 0; i < 2; ++i)
#pragma unroll
            for (int j = 0; j < 2; ++j)
#pragma unroll
                for (int k = 0; k < 4; ++k) c[i][j][k] = 0.f;

        const char* vh = sm + XBUF(cur, 0);
        const char* vl = sm + XBUF(cur, 1);
#pragma unroll
        for (int ks = 0; ks < 8; ++ks) {
            const int d = ks * 16 + 2 * tig;
#pragma unroll
            for (int ntl = 0; ntl < 2; ++ntl) {
                const int row = ngrp * 16 + ntl * 8 + gid;
                const uint32_t bh0 = *(const uint32_t*)(vh + row * PITCH + 2 * d);
                const uint32_t bh1 = *(const uint32_t*)(vh + row * PITCH + 2 * (d + 8));
                const uint32_t bl0 = *(const uint32_t*)(vl + row * PITCH + 2 * d);
                const uint32_t bl1 = *(const uint32_t*)(vl + row * PITCH + 2 * (d + 8));
                mma16816(c[0][ntl], ahi[0][ks], bh0, bh1);
                mma16816(c[1][ntl], ahi[1][ks], bh0, bh1);
                mma16816(c[0][ntl], ahi[0][ks], bl0, bl1);
                mma16816(c[1][ntl], ahi[1][ks], bl0, bl1);
                mma16816(c[0][ntl], alo[0][ks], bh0, bh1);
                mma16816(c[1][ntl], alo[1][ks], bh0, bh1);
            }
        }

        // ---- store xk ----
        const long long rbase = (tile0 + it) * P1_ROWS;
#pragma unroll
        for (int mt = 0; mt < 2; ++mt)
#pragma unroll
            for (int ntl = 0; ntl < 2; ++ntl) {
                const int r0 = ngrp * 16 + ntl * 8 + 2 * tig, r1 = r0 + 1;
                const int us0 = u0 + mt * 16 + gid, us1 = us0 + 8;
                g_xk[(rbase + r0) * NU + us0] = c[mt][ntl][0];
                g_xk[(rbase + r1) * NU + us0] = c[mt][ntl][1];
                g_xk[(rbase + r0) * NU + us1] = c[mt][ntl][2];
                g_xk[(rbase + r1) * NU + us1] = c[mt][ntl][3];
            }
        cur ^= 1;
    }
}

// =================== Phase 2: scan h_t = xk_t + h_{t-1}@R ===================
__global__ __launch_bounds__(256, 1)
void scan_kernel(const float* __restrict__ R, float* __restrict__ out) {
    extern __shared__ char sm[];
    const int tid  = threadIdx.x;
    const int lane = tid & 31;
    const int wid  = tid >> 5;
    const int gid  = lane >> 2, tig = lane & 3;
    const int mgrp = wid & 3, ngrp = wid >> 2;
    const int u0   = mgrp * 32;

    const int brow    = blockIdx.x * ROWS;
    const int chunk   = blockIdx.y;
    const int t_start = chunk * CHUNK;
    const int t0      = (chunk == 0) ? 0 : (t_start - WARM);
    const int t_end   = t_start + CHUNK;

    uint32_t ahi[2][8][4], alo[2][8][4];
    build_w_regs(R, ahi, alo, u0, gid, tig);

    // zero h buffer 0 (hi+lo): 2*ROWS*PITCH = 17408 B = 4352 words
#pragma unroll
    for (int i = 0; i < 17; ++i) ((uint32_t*)sm)[tid + i * 256] = 0;
    __syncthreads();

    int cur = 0;
    for (int t = t0; t < t_end; ++t) {
        const bool hn = (t + 1 < t_end);

        // ---- prefetch xk (LDG early, consumed after MMA) ----
        float xkr[16];
#pragma unroll
        for (int mt = 0; mt < 2; ++mt)
#pragma unroll
            for (int ntl = 0; ntl < 2; ++ntl) {
                const int r0 = ngrp * 16 + ntl * 8 + 2 * tig;
                const int us0 = u0 + mt * 16 + gid;
                const long long base0 = ((long long)(brow + r0) * NT + t) * NU;
                const long long base1 = base0 + (long long)NT * NU;
                const int q = (mt * 2 + ntl) * 4;
                xkr[q + 0] = g_xk[base0 + us0];
                xkr[q + 1] = g_xk[base1 + us0];
                xkr[q + 2] = g_xk[base0 + us0 + 8];
                xkr[q + 3] = g_xk[base1 + us0 + 8];
            }

        // ---- h @ R ----
        float c[2][2][4];
#pragma unroll
        for (int i = 0; i < 2; ++i)
#pragma unroll
            for (int j = 0; j < 2; ++j)
#pragma unroll
                for (int k = 0; k < 4; ++k) c[i][j][k] = 0.f;

        const char* vh = sm + HB(cur, 0);
        const char* vl = sm + HB(cur, 1);
#pragma unroll
        for (int ks = 0; ks < 8; ++ks) {
            const int d = ks * 16 + 2 * tig;
#pragma unroll
            for (int ntl = 0; ntl < 2; ++ntl) {
                const int row = ngrp * 16 + ntl * 8 + gid;
                const uint32_t bh0 = *(const uint32_t*)(vh + row * PITCH + 2 * d);
                const uint32_t bh1 = *(const uint32_t*)(vh + row * PITCH + 2 * (d + 8));
                const uint32_t bl0 = *(const uint32_t*)(vl + row * PITCH + 2 * d);
                const uint32_t bl1 = *(const uint32_t*)(vl + row * PITCH + 2 * (d + 8));
                mma16816(c[0][ntl], ahi[0][ks], bh0, bh1);
                mma16816(c[1][ntl], ahi[1][ks], bh0, bh1);
                mma16816(c[0][ntl], ahi[0][ks], bl0, bl1);
                mma16816(c[1][ntl], ahi[1][ks], bl0, bl1);
                mma16816(c[0][ntl], alo[0][ks], bh0, bh1);
                mma16816(c[1][ntl], alo[1][ks], bh0, bh1);
            }
        }

        // ---- h = xk + h@R ; feedback ; emit ----
        char* nh = sm + HB(cur ^ 1, 0);
        char* nl = sm + HB(cur ^ 1, 1);
        const bool emit = (t >= t_start);
#pragma unroll
        for (int mt = 0; mt < 2; ++mt)
#pragma unroll
            for (int ntl = 0; ntl < 2; ++ntl) {
                const int r0 = ngrp * 16 + ntl * 8 + 2 * tig, r1 = r0 + 1;
                const int us0 = u0 + mt * 16 + gid, us1 = us0 + 8;
                const int q = (mt * 2 + ntl) * 4;
                const float h0 = c[mt][ntl][0] + xkr[q + 0];
                const float h1 = c[mt][ntl][1] + xkr[q + 1];
                const float h2 = c[mt][ntl][2] + xkr[q + 2];
                const float h3 = c[mt][ntl][3] + xkr[q + 3];
                if (hn) {
                    __half h, l;
                    h = __float2half_rn(h0); l = __float2half_rn(h0 - __half2float(h));
                    *(__half*)(nh + r0 * PITCH + 2 * us0) = h;
                    *(__half*)(nl + r0 * PITCH + 2 * us0) = l;
                    h = __float2half_rn(h1); l = __float2half_rn(h1 - __half2float(h));
                    *(__half*)(nh + r1 * PITCH + 2 * us0) = h;
                    *(__half*)(nl + r1 * PITCH + 2 * us0) = l;
                    h = __float2half_rn(h2); l = __float2half_rn(h2 - __half2float(h));
                    *(__half*)(nh + r0 * PITCH + 2 * us1) = h;
                    *(__half*)(nl + r0 * PITCH + 2 * us1) = l;
                    h = __float2half_rn(h3); l = __float2half_rn(h3 - __half2float(h));
                    *(__half*)(nh + r1 * PITCH + 2 * us1) = h;
                    *(__half*)(nl + r1 * PITCH + 2 * us1) = l;
                }
                if (emit) {
                    out[((long long)(brow + r0) * NT + t) * NU + us0] = h0;
                    out[((long long)(brow + r1) * NT + t) * NU + us0] = h1;
                    out[((long long)(brow + r0) * NT + t) * NU + us1] = h2;
                    out[((long long)(brow + r1) * NT + t) * NU + us1] = h3;
                }
            }

        __syncthreads();
        cur ^= 1;
    }
}

extern "C" void kernel_launch(void* const* d_in, const int* in_sizes, int n_in,
                              void* d_out, int out_size) {
    const float* x = (const float*)d_in[0];
    const float* K = (const float*)d_in[1];
    const float* R = (const float*)d_in[2];
    float* out = (float*)d_out;

    cudaFuncSetAttribute(xk_kernel,
                         cudaFuncAttributeMaxDynamicSharedMemorySize, SMEM1);
    cudaFuncSetAttribute(scan_kernel,
                         cudaFuncAttributeMaxDynamicSharedMemorySize, SMEM2);

    xk_kernel<<<P1_GRID, 256, SMEM1>>>(x, K);
    dim3 grid2(NB / ROWS, NT / CHUNK);  // 8 x 16 = 128 blocks, one wave
    scan_kernel<<<grid2, 256, SMEM2>>>(R, out);
}

// round 8
// speedup vs baseline: 1.0520x; 1.0520x over previous
#include <cuda_runtime.h>
#include <cuda_fp16.h>
#include <cstdint>

// MinimalRNNCell, two-phase, occupancy-focused (R8):
//   Phase 1: g_xk = x @ K                  (256 thr, 2 CTAs/SM -> 16 warps/SM)
//   Phase 2: h_t = g_xk[t] + h_{t-1} @ R   (512 thr, 16 warps, chunked scan)
// mma.sync.m16n8k16, fp16 hi/lo x3 (Ahi*Bhi + Ahi*Blo + Alo*Bhi), err ~2^-22.
// M-split 8: 16 u per warp -> weight frags hi+lo = 64 regs/thread, total
// ~100-120 regs -> 16 warps/SM (prior rounds: 254 regs, 8 warps, issue 23%).

#define NB 256
#define NT 2048
#define ND 128
#define NU 128
#define BT (NB * NT)          // 524288
#define ROWS 32
#define CHUNK 128
#define WARM 32

#define PITCH 272             // bytes/row; (272/4)%32==4 -> conflict-free frags

// Phase 1
#define P1_ROWS 32
#define P1_TPB  8
#define P1_GRID (BT / P1_ROWS / P1_TPB)   // 2048
#define XBUF(b, hl) (((b) * 2 + (hl)) * (P1_ROWS * PITCH))
#define SMEM1 (4 * P1_ROWS * PITCH)       // 34816

// Phase 2
#define HB(b, hl) (((b) * 2 + (hl)) * (ROWS * PITCH))
#define SMEM2 (4 * ROWS * PITCH)          // 34816

__device__ float g_xk[(size_t)BT * NU];   // 268 MB scratch

__device__ __forceinline__ void mma16816(float* c, const uint32_t* a,
                                         uint32_t b0, uint32_t b1) {
    asm("mma.sync.aligned.m16n8k16.row.col.f32.f16.f16.f32 "
        "{%0,%1,%2,%3}, {%4,%5,%6,%7}, {%8,%9}, {%0,%1,%2,%3};"
        : "+f"(c[0]), "+f"(c[1]), "+f"(c[2]), "+f"(c[3])
        : "r"(a[0]), "r"(a[1]), "r"(a[2]), "r"(a[3]), "r"(b0), "r"(b1));
}

__device__ __forceinline__ uint32_t pack_hilo(float f0, float f1, uint32_t* lo) {
    __half h0 = __float2half_rn(f0), h1 = __float2half_rn(f1);
    __half l0 = __float2half_rn(f0 - __half2float(h0));
    __half l1 = __float2half_rn(f1 - __half2float(h1));
    *lo = (uint32_t)__half_as_ushort(l0) | ((uint32_t)__half_as_ushort(l1) << 16);
    return (uint32_t)__half_as_ushort(h0) | ((uint32_t)__half_as_ushort(h1) << 16);
}

// Weight frags (hi+lo) for a 16-u slice of 128x128 W[d][u]: 64 regs.
__device__ __forceinline__ void build_w16(const float* __restrict__ W,
                                          uint32_t ahi[8][4], uint32_t alo[8][4],
                                          int u0, int gid, int tig) {
    const int ur0 = u0 + gid, ur1 = ur0 + 8;
#pragma unroll
    for (int ks = 0; ks < 8; ++ks) {
        const int d = ks * 16 + 2 * tig;
        ahi[ks][0] = pack_hilo(W[d * NU + ur0], W[(d + 1) * NU + ur0], &alo[ks][0]);
        ahi[ks][1] = pack_hilo(W[d * NU + ur1], W[(d + 1) * NU + ur1], &alo[ks][1]);
        ahi[ks][2] = pack_hilo(W[(d + 8) * NU + ur0], W[(d + 9) * NU + ur0], &alo[ks][2]);
        ahi[ks][3] = pack_hilo(W[(d + 8) * NU + ur1], W[(d + 9) * NU + ur1], &alo[ks][3]);
    }
}

// =================== Phase 1: g_xk = x @ K ===================
__global__ __launch_bounds__(256, 2)
void xk_kernel(const float* __restrict__ x, const float* __restrict__ K) {
    extern __shared__ char sm[];
    const int tid  = threadIdx.x;
    const int lane = tid & 31;
    const int wid  = tid >> 5;            // 0..7 = M-group
    const int gid  = lane >> 2, tig = lane & 3;
    const int u0   = wid * 16;

    uint32_t ahi[8][4], alo[8][4];
    build_w16(K, ahi, alo, u0, gid, tig);

    const long long tile0 = (long long)blockIdx.x * P1_TPB;
    const float4* x4 = (const float4*)x;

    float4 px[4];
#pragma unroll
    for (int j = 0; j < 4; ++j) {
        const int idx = tid + j * 256;
        px[j] = x4[(tile0 * P1_ROWS + (idx >> 5)) * 32 + (idx & 31)];
    }

    int cur = 0;
    for (int it = 0; it < P1_TPB; ++it) {
        // ---- stage prefetched x tile (hi/lo) ----
#pragma unroll
        for (int j = 0; j < 4; ++j) {
            const int idx = tid + j * 256;
            const int r = idx >> 5, c4 = idx & 31;
            uint32_t lo0, lo1;
            const uint32_t h0 = pack_hilo(px[j].x, px[j].y, &lo0);
            const uint32_t h1 = pack_hilo(px[j].z, px[j].w, &lo1);
            char* bh = sm + XBUF(cur, 0) + r * PITCH + c4 * 8;
            char* bl = sm + XBUF(cur, 1) + r * PITCH + c4 * 8;
            *(uint32_t*)bh = h0;  *(uint32_t*)(bh + 4) = h1;
            *(uint32_t*)bl = lo0; *(uint32_t*)(bl + 4) = lo1;
        }
        __syncthreads();

        // ---- prefetch next tile (hidden under MMA) ----
        if (it + 1 < P1_TPB) {
#pragma unroll
            for (int j = 0; j < 4; ++j) {
                const int idx = tid + j * 256;
                px[j] = x4[((tile0 + it + 1) * P1_ROWS + (idx >> 5)) * 32 + (idx & 31)];
            }
        }

        // ---- MMA: 16 u x 32 rows per warp ----
        float c[4][4];
#pragma unroll
        for (int j = 0; j < 4; ++j)
#pragma unroll
            for (int k = 0; k < 4; ++k) c[j][k] = 0.f;

        const char* vh = sm + XBUF(cur, 0);
        const char* vl = sm + XBUF(cur, 1);
#pragma unroll
        for (int ks = 0; ks < 8; ++ks) {
            const int d = ks * 16 + 2 * tig;
#pragma unroll
            for (int nt = 0; nt < 4; ++nt) {
                const int row = nt * 8 + gid;
                const uint32_t bh0 = *(const uint32_t*)(vh + row * PITCH + 2 * d);
                const uint32_t bh1 = *(const uint32_t*)(vh + row * PITCH + 2 * (d + 8));
                const uint32_t bl0 = *(const uint32_t*)(vl + row * PITCH + 2 * d);
                const uint32_t bl1 = *(const uint32_t*)(vl + row * PITCH + 2 * (d + 8));
                mma16816(c[nt], ahi[ks], bh0, bh1);
                mma16816(c[nt], ahi[ks], bl0, bl1);
                mma16816(c[nt], alo[ks], bh0, bh1);
            }
        }

        // ---- store xk ----
        const long long rbase = (tile0 + it) * P1_ROWS;
#pragma unroll
        for (int nt = 0; nt < 4; ++nt) {
            const int r0 = nt * 8 + 2 * tig, r1 = r0 + 1;
            const int us0 = u0 + gid, us1 = us0 + 8;
            g_xk[(rbase + r0) * NU + us0] = c[nt][0];
            g_xk[(rbase + r1) * NU + us0] = c[nt][1];
            g_xk[(rbase + r0) * NU + us1] = c[nt][2];
            g_xk[(rbase + r1) * NU + us1] = c[nt][3];
        }
        cur ^= 1;
    }
}

// =================== Phase 2: scan h_t = xk_t + h_{t-1}@R ===================
__global__ __launch_bounds__(512, 1)
void scan_kernel(const float* __restrict__ R, float* __restrict__ out) {
    extern __shared__ char sm[];
    const int tid  = threadIdx.x;
    const int lane = tid & 31;
    const int wid  = tid >> 5;            // 0..15
    const int gid  = lane >> 2, tig = lane & 3;
    const int mgrp = wid & 7, ngrp = wid >> 3;
    const int u0   = mgrp * 16;

    const int brow    = blockIdx.x * ROWS;
    const int chunk   = blockIdx.y;
    const int t_start = chunk * CHUNK;
    const int t0      = (chunk == 0) ? 0 : (t_start - WARM);
    const int t_end   = t_start + CHUNK;

    uint32_t ahi[8][4], alo[8][4];
    build_w16(R, ahi, alo, u0, gid, tig);

    // zero h buffer 0 (hi+lo): 2*ROWS*PITCH = 17408 B = 4352 words
#pragma unroll
    for (int i = 0; i < 9; ++i) {
        const int idx = tid + i * 512;
        if (idx < 4352) ((uint32_t*)sm)[idx] = 0;
    }
    __syncthreads();

    int cur = 0;
    for (int t = t0; t < t_end; ++t) {
        const bool hn = (t + 1 < t_end);

        // ---- prefetch xk (LDG early, consumed after MMA) ----
        float xkr[8];
#pragma unroll
        for (int ntl = 0; ntl < 2; ++ntl) {
            const int r0 = ngrp * 16 + ntl * 8 + 2 * tig;
            const int us0 = u0 + gid;
            const long long base0 = ((long long)(brow + r0) * NT + t) * NU;
            const long long base1 = base0 + (long long)NT * NU;
            xkr[ntl * 4 + 0] = g_xk[base0 + us0];
            xkr[ntl * 4 + 1] = g_xk[base1 + us0];
            xkr[ntl * 4 + 2] = g_xk[base0 + us0 + 8];
            xkr[ntl * 4 + 3] = g_xk[base1 + us0 + 8];
        }

        // ---- h @ R ----
        float c[2][4];
#pragma unroll
        for (int j = 0; j < 2; ++j)
#pragma unroll
            for (int k = 0; k < 4; ++k) c[j][k] = 0.f;

        const char* vh = sm + HB(cur, 0);
        const char* vl = sm + HB(cur, 1);
#pragma unroll
        for (int ks = 0; ks < 8; ++ks) {
            const int d = ks * 16 + 2 * tig;
#pragma unroll
            for (int ntl = 0; ntl < 2; ++ntl) {
                const int row = ngrp * 16 + ntl * 8 + gid;
                const uint32_t bh0 = *(const uint32_t*)(vh + row * PITCH + 2 * d);
                const uint32_t bh1 = *(const uint32_t*)(vh + row * PITCH + 2 * (d + 8));
                const uint32_t bl0 = *(const uint32_t*)(vl + row * PITCH + 2 * d);
                const uint32_t bl1 = *(const uint32_t*)(vl + row * PITCH + 2 * (d + 8));
                mma16816(c[ntl], ahi[ks], bh0, bh1);
                mma16816(c[ntl], ahi[ks], bl0, bl1);
                mma16816(c[ntl], alo[ks], bh0, bh1);
            }
        }

        // ---- h = xk + h@R ; feedback ; emit ----
        char* nh = sm + HB(cur ^ 1, 0);
        char* nl = sm + HB(cur ^ 1, 1);
        const bool emit = (t >= t_start);
#pragma unroll
        for (int ntl = 0; ntl < 2; ++ntl) {
            const int r0 = ngrp * 16 + ntl * 8 + 2 * tig, r1 = r0 + 1;
            const int us0 = u0 + gid, us1 = us0 + 8;
            const float h0 = c[ntl][0] + xkr[ntl * 4 + 0];
            const float h1 = c[ntl][1] + xkr[ntl * 4 + 1];
            const float h2 = c[ntl][2] + xkr[ntl * 4 + 2];
            const float h3 = c[ntl][3] + xkr[ntl * 4 + 3];
            if (hn) {
                __half h, l;
                h = __float2half_rn(h0); l = __float2half_rn(h0 - __half2float(h));
                *(__half*)(nh + r0 * PITCH + 2 * us0) = h;
                *(__half*)(nl + r0 * PITCH + 2 * us0) = l;
                h = __float2half_rn(h1); l = __float2half_rn(h1 - __half2float(h));
                *(__half*)(nh + r1 * PITCH + 2 * us0) = h;
                *(__half*)(nl + r1 * PITCH + 2 * us0) = l;
                h = __float2half_rn(h2); l = __float2half_rn(h2 - __half2float(h));
                *(__half*)(nh + r0 * PITCH + 2 * us1) = h;
                *(__half*)(nl + r0 * PITCH + 2 * us1) = l;
                h = __float2half_rn(h3); l = __float2half_rn(h3 - __half2float(h));
                *(__half*)(nh + r1 * PITCH + 2 * us1) = h;
                *(__half*)(nl + r1 * PITCH + 2 * us1) = l;
            }
            if (emit) {
                out[((long long)(brow + r0) * NT + t) * NU + us0] = h0;
                out[((long long)(brow + r1) * NT + t) * NU + us0] = h1;
                out[((long long)(brow + r0) * NT + t) * NU + us1] = h2;
                out[((long long)(brow + r1) * NT + t) * NU + us1] = h3;
            }
        }

        __syncthreads();
        cur ^= 1;
    }
}

extern "C" void kernel_launch(void* const* d_in, const int* in_sizes, int n_in,
                              void* d_out, int out_size) {
    const float* x = (const float*)d_in[0];
    const float* K = (const float*)d_in[1];
    const float* R = (const float*)d_in[2];
    float* out = (float*)d_out;

    cudaFuncSetAttribute(xk_kernel,
                         cudaFuncAttributeMaxDynamicSharedMemorySize, SMEM1);
    cudaFuncSetAttribute(scan_kernel,
                         cudaFuncAttributeMaxDynamicSharedMemorySize, SMEM2);

    xk_kernel<<<P1_GRID, 256, SMEM1>>>(x, K);
    dim3 grid2(NB / ROWS, NT / CHUNK);  // 8 x 16 = 128 blocks, one wave
    scan_kernel<<<grid2, 512, SMEM2>>>(R, out);
}